// round 15
// baseline (speedup 1.0000x reference)
#include <cuda_runtime.h>
#include <cuda_fp16.h>
#include <cstdint>
#include <math.h>

// ---------------- problem constants ----------------
#define T_TOK 8192
#define D_DIM 1024
#define E_NUM 8
#define H_DIM 512
#define NSLOT (2 * T_TOK)

// ---------------- device scratch (referenced ONLY from device code) ------
__device__ int   g_count[E_NUM];          // static-zero init; re-zeroed by combine_kernel
__device__ int   g_entry[E_NUM][T_TOK];
__device__ float g_gateW[E_NUM][T_TOK];
__device__ __align__(16) __half g_Xh[(size_t)T_TOK * D_DIM];           // fp16 x
__device__ __align__(16) __half g_w1h[(size_t)E_NUM * D_DIM * H_DIM];  // [e][d][h]
__device__ __align__(16) __half g_w3h[(size_t)E_NUM * D_DIM * H_DIM];  // [e][d][h]
__device__ __align__(16) __half g_w2h[(size_t)E_NUM * H_DIM * D_DIM];  // [e][h][d]
__device__ __align__(16) __half g_U[(size_t)NSLOT * H_DIM];            // SwiGLU hidden fp16
__device__ __align__(16) __half g_Y[(size_t)NSLOT * D_DIM];            // gated down-proj fp16

// ---------------- helpers (sm_80-level PTX only) ----
__device__ __forceinline__ uint32_t smem_u32(const void* p) {
    uint32_t a;
    asm("{ .reg .u64 t; cvta.to.shared.u64 t, %1; cvt.u32.u64 %0, t; }" : "=r"(a) : "l"(p));
    return a;
}
__device__ __forceinline__ void cp16(uint32_t dst, const void* src) {
    asm volatile("cp.async.cg.shared.global [%0], [%1], 16;" :: "r"(dst), "l"(src));
}
#define CP_COMMIT() asm volatile("cp.async.commit_group;" ::: "memory")
#define CP_WAIT1()  asm volatile("cp.async.wait_group 1;" ::: "memory")

__device__ __forceinline__ void ldsm4(uint32_t* r, uint32_t addr) {
    asm volatile("ldmatrix.sync.aligned.m8n8.x4.shared.b16 {%0,%1,%2,%3}, [%4];"
        : "=r"(r[0]), "=r"(r[1]), "=r"(r[2]), "=r"(r[3]) : "r"(addr));
}
__device__ __forceinline__ void ldsm4t(uint32_t* r, uint32_t addr) {
    asm volatile("ldmatrix.sync.aligned.m8n8.x4.trans.shared.b16 {%0,%1,%2,%3}, [%4];"
        : "=r"(r[0]), "=r"(r[1]), "=r"(r[2]), "=r"(r[3]) : "r"(addr));
}
__device__ __forceinline__ void mma16(float* c, const uint32_t* a, const uint32_t* b) {
    asm volatile(
        "mma.sync.aligned.m16n8k16.row.col.f32.f16.f16.f32 "
        "{%0,%1,%2,%3}, {%4,%5,%6,%7}, {%8,%9}, {%0,%1,%2,%3};"
        : "+f"(c[0]), "+f"(c[1]), "+f"(c[2]), "+f"(c[3])
        : "r"(a[0]), "r"(a[1]), "r"(a[2]), "r"(a[3]), "r"(b[0]), "r"(b[1]));
}

// ---------------- kernel: fused weight-convert + router ----------------
// blocks [0, WCONV_BLKS): fp16-convert w1/w2/w3 (1 float4 strip each)
// blocks [WCONV_BLKS, WCONV_BLKS + T_TOK/8): router, 8 tokens per block
#define WCONV_BLKS 4096
__global__ __launch_bounds__(256) void prep_kernel(const float* __restrict__ x,
                                                   const float* __restrict__ wr,
                                                   const float* __restrict__ w1,
                                                   const float* __restrict__ w2,
                                                   const float* __restrict__ w3) {
    __shared__ float sWr[D_DIM * E_NUM];   // used only by router blocks (32KB)

    if (blockIdx.x < WCONV_BLKS) {
        size_t i4 = (size_t)blockIdx.x * 256 + threadIdx.x;
        size_t n4 = (size_t)E_NUM * D_DIM * H_DIM / 4;
        if (i4 >= n4) return;
        {
            float4 v = *(const float4*)(w1 + i4 * 4);
            __half2 h0 = __floats2half2_rn(v.x, v.y), h1 = __floats2half2_rn(v.z, v.w);
            *(uint2*)(g_w1h + i4 * 4) = make_uint2(*(uint32_t*)&h0, *(uint32_t*)&h1);
        }
        {
            float4 v = *(const float4*)(w3 + i4 * 4);
            __half2 h0 = __floats2half2_rn(v.x, v.y), h1 = __floats2half2_rn(v.z, v.w);
            *(uint2*)(g_w3h + i4 * 4) = make_uint2(*(uint32_t*)&h0, *(uint32_t*)&h1);
        }
        {
            float4 v = *(const float4*)(w2 + i4 * 4);
            __half2 h0 = __floats2half2_rn(v.x, v.y), h1 = __floats2half2_rn(v.z, v.w);
            *(uint2*)(g_w2h + i4 * 4) = make_uint2(*(uint32_t*)&h0, *(uint32_t*)&h1);
        }
        return;
    }

    // ---- router part ----
    for (int i = threadIdx.x; i < D_DIM * E_NUM; i += blockDim.x) sWr[i] = wr[i];
    __syncthreads();

    int warp = threadIdx.x >> 5, lane = threadIdx.x & 31;
    int t = (blockIdx.x - WCONV_BLKS) * 8 + warp;
    if (t >= T_TOK) return;

    float acc[E_NUM];
#pragma unroll
    for (int e = 0; e < E_NUM; e++) acc[e] = 0.f;
    const float* xr = x + (size_t)t * D_DIM;
    __half* xo = g_Xh + (size_t)t * D_DIM;
    for (int d = lane; d < D_DIM; d += 32) {
        float xv = xr[d];
        xo[d] = __float2half_rn(xv);
#pragma unroll
        for (int e = 0; e < E_NUM; e++) acc[e] = fmaf(xv, sWr[d * E_NUM + e], acc[e]);
    }
#pragma unroll
    for (int off = 16; off > 0; off >>= 1)
#pragma unroll
        for (int e = 0; e < E_NUM; e++) acc[e] += __shfl_down_sync(0xffffffffu, acc[e], off);

    if (lane == 0) {
        float m = acc[0];
#pragma unroll
        for (int e = 1; e < E_NUM; e++) m = fmaxf(m, acc[e]);
        float p[E_NUM], s = 0.f;
#pragma unroll
        for (int e = 0; e < E_NUM; e++) { p[e] = expf(acc[e] - m); s += p[e]; }
        float inv = 1.f / s;
#pragma unroll
        for (int e = 0; e < E_NUM; e++) p[e] *= inv;

        int e0 = 0;
#pragma unroll
        for (int e = 1; e < E_NUM; e++) if (p[e] > p[e0]) e0 = e;
        int e1 = (e0 == 0) ? 1 : 0;
#pragma unroll
        for (int e = 0; e < E_NUM; e++) {
            if (e == e0) continue;
            if (p[e] > p[e1]) e1 = e;
        }
        int pos0 = atomicAdd(&g_count[e0], 1);
        g_entry[e0][pos0] = t * 2 + 0;
        g_gateW[e0][pos0] = p[e0];
        int pos1 = atomicAdd(&g_count[e1], 1);
        g_entry[e1][pos1] = t * 2 + 1;
        g_gateW[e1][pos1] = p[e1];
    }
}

// ---------------- GEMM tiling constants (R12 config) ----------------
#define BKT 64                          // K per smem tile (halves)
#define ASTR 144                        // A smem row stride bytes
#define BUSTR 144                       // up B k-row stride
#define BDSTR 272                       // down B k-row stride
#define A_TILE_B (128 * ASTR)           // 18432
#define BU_TILE_B (BKT * BUSTR)         // 9216 (per weight)
#define BD_TILE_B (BKT * BDSTR)         // 17408
#define STAGE_U (A_TILE_B + 2 * BU_TILE_B)  // 36864
#define STAGE_D (A_TILE_B + BD_TILE_B)      // 35840
#define UP_SMEM   (3 * STAGE_U)             // 110592
#define DOWN_SMEM (3 * STAGE_D)             // 107520

// ============================================================
// UP: per expert, U = silu(Xg@W1)*(Xg@W3). CTA: M=128, N=64 (each), K=1024.
// 3-stage ring, one barrier per k-iter. 256 thr, 2 CTAs/SM.
// ============================================================
__global__ __launch_bounds__(256, 2) void up_gemm_kernel() {
    const int e = blockIdx.z;
    const int count = g_count[e];
    const int m0 = blockIdx.x * 128;
    if (m0 >= count) return;
    const int n0 = blockIdx.y * 64;

    extern __shared__ __align__(128) char smem[];
    __shared__ int sTok[128];
    __shared__ int sEnt[128];

    const int tid = threadIdx.x;
    const int wid = tid >> 5, lane = tid & 31;
    const int warp_m = wid >> 1, warp_n = wid & 1;

    uint32_t base = smem_u32(smem);

    if (tid < 128) {
        int p = m0 + tid;
        int ent = (p < count) ? g_entry[e][p] : g_entry[e][0];
        sEnt[tid] = ent;
        sTok[tid] = ent >> 1;
    }
    __syncthreads();

    const __half* W1 = g_w1h + (size_t)e * D_DIM * H_DIM;   // [d][h] = [k][n]
    const __half* W3 = g_w3h + (size_t)e * D_DIM * H_DIM;

    auto load_tile = [&](int buf, int k0) {      // k0 in halves
        uint32_t aB  = base + buf * STAGE_U;
        uint32_t b1B = aB + A_TILE_B;
        uint32_t b3B = b1B + BU_TILE_B;
#pragma unroll
        for (int i = 0; i < 4; i++) {            // A: 128 m-rows x 8 chunks
            int c = tid + i * 256, row = c >> 3, q = c & 7;
            cp16(aB + row * ASTR + q * 16,
                 g_Xh + (size_t)sTok[row] * D_DIM + k0 + q * 8);
        }
#pragma unroll
        for (int i = 0; i < 2; i++) {            // B1: 64 k-rows x 8 chunks
            int c = tid + i * 256, row = c >> 3, q = c & 7;
            cp16(b1B + row * BUSTR + q * 16,
                 W1 + (size_t)(k0 + row) * H_DIM + n0 + q * 8);
        }
#pragma unroll
        for (int i = 0; i < 2; i++) {            // B3
            int c = tid + i * 256, row = c >> 3, q = c & 7;
            cp16(b3B + row * BUSTR + q * 16,
                 W3 + (size_t)(k0 + row) * H_DIM + n0 + q * 8);
        }
    };

    load_tile(0, 0);       CP_COMMIT();
    load_tile(1, BKT);     CP_COMMIT();

    float acc1[2][4][4] = {};
    float acc3[2][4][4] = {};

    uint32_t aOff0 = (uint32_t)(warp_m * 32 + (lane & 15)) * ASTR + (lane >> 4) * 16;
    uint32_t aOff1 = aOff0 + 16 * ASTR;
    uint32_t bOffT = (uint32_t)((lane & 7) + ((lane >> 3) & 1) * 8) * BUSTR
                   + (uint32_t)(warp_n * 32 + ((lane >> 4) & 1) * 8) * 2;

    const int lrow = lane >> 2;
    const int lcol = lane & 3;
    const int NT = D_DIM / BKT;      // 16

    for (int kt = 0; kt < NT; kt++) {
        const int cur = kt % 3;
        CP_WAIT1();
        __syncthreads();
        if (kt + 2 < NT) load_tile((kt + 2) % 3, (kt + 2) * BKT);
        CP_COMMIT();

        uint32_t aS  = base + cur * STAGE_U;
        uint32_t b1S = aS + A_TILE_B;
        uint32_t b3S = b1S + BU_TILE_B;

#pragma unroll
        for (int ks = 0; ks < BKT / 16; ks++) {
            uint32_t a[2][4], b1[2][4], b3[2][4];
            ldsm4(a[0], aS + aOff0 + ks * 32);
            ldsm4(a[1], aS + aOff1 + ks * 32);
#pragma unroll
            for (int p = 0; p < 2; p++) {
                ldsm4t(b1[p], b1S + bOffT + p * 32 + ks * (16 * BUSTR));
                ldsm4t(b3[p], b3S + bOffT + p * 32 + ks * (16 * BUSTR));
            }
#pragma unroll
            for (int mt = 0; mt < 2; mt++)
#pragma unroll
                for (int p = 0; p < 2; p++) {
                    mma16(acc1[mt][2 * p + 0], a[mt], &b1[p][0]);
                    mma16(acc1[mt][2 * p + 1], a[mt], &b1[p][2]);
                    mma16(acc3[mt][2 * p + 0], a[mt], &b3[p][0]);
                    mma16(acc3[mt][2 * p + 1], a[mt], &b3[p][2]);
                }
        }
    }

    // epilogue: silu(u1)*u3 -> g_U (fp16); fast __expf (error ~1e-5 rel, << fp16 quantum)
#pragma unroll
    for (int mt = 0; mt < 2; mt++) {
#pragma unroll
        for (int half = 0; half < 2; half++) {
            int r = warp_m * 32 + mt * 16 + lrow + half * 8;
            if (m0 + r < count) {
                __half* urow = g_U + (size_t)sEnt[r] * H_DIM;
#pragma unroll
                for (int nt = 0; nt < 4; nt++) {
                    int cbase = n0 + warp_n * 32 + nt * 8 + 2 * lcol;
                    float z0 = acc1[mt][nt][half * 2 + 0];
                    float z1 = acc1[mt][nt][half * 2 + 1];
                    float u0 = z0 / (1.f + __expf(-z0)) * acc3[mt][nt][half * 2 + 0];
                    float u1 = z1 / (1.f + __expf(-z1)) * acc3[mt][nt][half * 2 + 1];
                    *(__half2*)(urow + cbase) = __floats2half2_rn(u0, u1);
                }
            }
        }
    }
}

// ============================================================
// DOWN: per expert, Y = gate * (U@W2) stored fp16 per (token,slot).
// CTA: M=128, N=128, K=512. 3-stage ring, one barrier per iter.
// ============================================================
__global__ __launch_bounds__(256, 2) void down_gemm_kernel() {
    const int e = blockIdx.z;
    const int count = g_count[e];
    const int m0 = blockIdx.x * 128;
    if (m0 >= count) return;
    const int n0 = blockIdx.y * 128;

    extern __shared__ __align__(128) char smem[];
    __shared__ int   sEnt[128];
    __shared__ float sGate[128];

    const int tid = threadIdx.x;
    const int wid = tid >> 5, lane = tid & 31;
    const int warp_m = wid >> 1, warp_n = wid & 1;

    uint32_t base = smem_u32(smem);

    if (tid < 128) {
        int p = m0 + tid;
        sEnt[tid]  = (p < count) ? g_entry[e][p] : g_entry[e][0];
        sGate[tid] = (p < count) ? g_gateW[e][p] : 0.f;
    }
    __syncthreads();

    const __half* W2 = g_w2h + (size_t)e * H_DIM * D_DIM;   // [h][d] = [k][n]

    auto load_tile = [&](int buf, int k0) {
        uint32_t aB = base + buf * STAGE_D;
        uint32_t bB = aB + A_TILE_B;
#pragma unroll
        for (int i = 0; i < 4; i++) {            // A: 128 m-rows x 8 chunks
            int c = tid + i * 256, row = c >> 3, q = c & 7;
            cp16(aB + row * ASTR + q * 16,
                 g_U + (size_t)sEnt[row] * H_DIM + k0 + q * 8);
        }
#pragma unroll
        for (int i = 0; i < 4; i++) {            // B: 64 k-rows x 16 chunks
            int c = tid + i * 256, row = c >> 4, q = c & 15;
            cp16(bB + row * BDSTR + q * 16,
                 W2 + (size_t)(k0 + row) * D_DIM + n0 + q * 8);
        }
    };

    load_tile(0, 0);       CP_COMMIT();
    load_tile(1, BKT);     CP_COMMIT();

    float acc[2][8][4] = {};

    uint32_t aOff0 = (uint32_t)(warp_m * 32 + (lane & 15)) * ASTR + (lane >> 4) * 16;
    uint32_t aOff1 = aOff0 + 16 * ASTR;
    uint32_t bOffT = (uint32_t)((lane & 7) + ((lane >> 3) & 1) * 8) * BDSTR
                   + (uint32_t)(warp_n * 64 + ((lane >> 4) & 1) * 8) * 2;

    const int lrow = lane >> 2;
    const int lcol = lane & 3;
    const int NT = H_DIM / BKT;   // 8

    for (int kt = 0; kt < NT; kt++) {
        const int cur = kt % 3;
        CP_WAIT1();
        __syncthreads();
        if (kt + 2 < NT) load_tile((kt + 2) % 3, (kt + 2) * BKT);
        CP_COMMIT();

        uint32_t aS = base + cur * STAGE_D;
        uint32_t bS = aS + A_TILE_B;

#pragma unroll
        for (int ks = 0; ks < BKT / 16; ks++) {
            uint32_t a[2][4], b[4][4];
            ldsm4(a[0], aS + aOff0 + ks * 32);
            ldsm4(a[1], aS + aOff1 + ks * 32);
#pragma unroll
            for (int p = 0; p < 4; p++)
                ldsm4t(b[p], bS + bOffT + p * 32 + ks * (16 * BDSTR));
#pragma unroll
            for (int mt = 0; mt < 2; mt++)
#pragma unroll
                for (int p = 0; p < 4; p++) {
                    mma16(acc[mt][2 * p + 0], a[mt], &b[p][0]);
                    mma16(acc[mt][2 * p + 1], a[mt], &b[p][2]);
                }
        }
    }

    // epilogue: fp16 store of gate*acc per slot
#pragma unroll
    for (int mt = 0; mt < 2; mt++) {
#pragma unroll
        for (int half = 0; half < 2; half++) {
            int r = warp_m * 32 + mt * 16 + lrow + half * 8;
            if (m0 + r < count) {
                float g = sGate[r];
                __half* yrow = g_Y + (size_t)sEnt[r] * D_DIM;
#pragma unroll
                for (int nt = 0; nt < 8; nt++) {
                    int cbase = n0 + warp_n * 64 + nt * 8 + 2 * lcol;
                    *(__half2*)(yrow + cbase) =
                        __floats2half2_rn(g * acc[mt][nt][half * 2 + 0],
                                          g * acc[mt][nt][half * 2 + 1]);
                }
            }
        }
    }
}

// ---------------- kernel: combine two fp16 slots + reset g_count --------
__global__ void combine_kernel(float* __restrict__ out) {
    // reset per-expert counters for the NEXT invocation (this kernel is the
    // last reader-free point; all g_count readers ran earlier in the sequence)
    if (blockIdx.x == 0 && threadIdx.x < E_NUM) g_count[threadIdx.x] = 0;

    size_t idx4 = (size_t)blockIdx.x * blockDim.x + threadIdx.x;
    size_t total4 = (size_t)T_TOK * D_DIM / 4;
    if (idx4 >= total4) return;
    size_t bofs = idx4 * 4;
    size_t t = bofs >> 10;
    size_t d = bofs & (D_DIM - 1);
    const uint2 pa = *(const uint2*)(g_Y + ((size_t)(2 * t) * D_DIM + d));
    const uint2 pb = *(const uint2*)(g_Y + ((size_t)(2 * t + 1) * D_DIM + d));
    float2 a0 = __half22float2(*(const __half2*)&pa.x);
    float2 a1 = __half22float2(*(const __half2*)&pa.y);
    float2 b0 = __half22float2(*(const __half2*)&pb.x);
    float2 b1 = __half22float2(*(const __half2*)&pb.y);
    float4 r;
    r.x = a0.x + b0.x; r.y = a0.y + b0.y;
    r.z = a1.x + b1.x; r.w = a1.y + b1.y;
    asm volatile("st.global.cs.v4.f32 [%0], {%1,%2,%3,%4};"
                 :: "l"(out + bofs), "f"(r.x), "f"(r.y), "f"(r.z), "f"(r.w) : "memory");
}

// ---------------- launch ----------------
extern "C" void kernel_launch(void* const* d_in, const int* in_sizes, int n_in,
                              void* d_out, int out_size) {
    const float* x  = (const float*)d_in[0];
    const float* wr = (const float*)d_in[1];
    const float* w1 = (const float*)d_in[2];
    const float* w2 = (const float*)d_in[3];
    const float* w3 = (const float*)d_in[4];
    float* out = (float*)d_out;

    cudaFuncSetAttribute(up_gemm_kernel,   cudaFuncAttributeMaxDynamicSharedMemorySize, UP_SMEM);
    cudaFuncSetAttribute(down_gemm_kernel, cudaFuncAttributeMaxDynamicSharedMemorySize, DOWN_SMEM);

    // fused weight-convert + router (g_count starts zeroed: static init on
    // first call, combine_kernel tail-reset on every subsequent sequence)
    prep_kernel<<<WCONV_BLKS + T_TOK / 8, 256>>>(x, wr, w1, w2, w3);

    {
        dim3 g(T_TOK / 128, H_DIM / 64, E_NUM);   // (64, 8, 8)
        up_gemm_kernel<<<g, 256, UP_SMEM>>>();
    }
    {
        dim3 g(T_TOK / 128, D_DIM / 128, E_NUM);  // (64, 8, 8)
        down_gemm_kernel<<<g, 256, DOWN_SMEM>>>();
    }

    size_t total4 = (size_t)T_TOK * D_DIM / 4;
    combine_kernel<<<(unsigned)((total4 + 255) / 256), 256>>>(out);
}

// round 16
// speedup vs baseline: 1.0113x; 1.0113x over previous
#include <cuda_runtime.h>
#include <cuda_fp16.h>
#include <cstdint>
#include <math.h>

// ---------------- problem constants ----------------
#define T_TOK 8192
#define D_DIM 1024
#define E_NUM 8
#define H_DIM 512
#define NSLOT (2 * T_TOK)

// ---------------- device scratch (referenced ONLY from device code) ------
__device__ int   g_count[E_NUM];          // static-zero init; re-zeroed by combine_kernel
__device__ int   g_entry[E_NUM][T_TOK];
__device__ float g_gateW[E_NUM][T_TOK];
__device__ __align__(16) __half g_Xh[(size_t)T_TOK * D_DIM];           // fp16 x
__device__ __align__(16) __half g_w1h[(size_t)E_NUM * D_DIM * H_DIM];  // [e][d][h]
__device__ __align__(16) __half g_w3h[(size_t)E_NUM * D_DIM * H_DIM];  // [e][d][h]
__device__ __align__(16) __half g_w2h[(size_t)E_NUM * H_DIM * D_DIM];  // [e][h][d]
__device__ __align__(16) __half g_U[(size_t)NSLOT * H_DIM];            // SwiGLU hidden fp16
__device__ __align__(16) __half g_Y[(size_t)NSLOT * D_DIM];            // gated down-proj fp16

// ---------------- helpers (sm_80-level PTX only) ----
__device__ __forceinline__ uint32_t smem_u32(const void* p) {
    uint32_t a;
    asm("{ .reg .u64 t; cvta.to.shared.u64 t, %1; cvt.u32.u64 %0, t; }" : "=r"(a) : "l"(p));
    return a;
}
__device__ __forceinline__ void cp16(uint32_t dst, const void* src) {
    asm volatile("cp.async.cg.shared.global [%0], [%1], 16;" :: "r"(dst), "l"(src));
}
#define CP_COMMIT() asm volatile("cp.async.commit_group;" ::: "memory")
#define CP_WAIT1()  asm volatile("cp.async.wait_group 1;" ::: "memory")

__device__ __forceinline__ void ldsm4(uint32_t* r, uint32_t addr) {
    asm volatile("ldmatrix.sync.aligned.m8n8.x4.shared.b16 {%0,%1,%2,%3}, [%4];"
        : "=r"(r[0]), "=r"(r[1]), "=r"(r[2]), "=r"(r[3]) : "r"(addr));
}
__device__ __forceinline__ void ldsm4t(uint32_t* r, uint32_t addr) {
    asm volatile("ldmatrix.sync.aligned.m8n8.x4.trans.shared.b16 {%0,%1,%2,%3}, [%4];"
        : "=r"(r[0]), "=r"(r[1]), "=r"(r[2]), "=r"(r[3]) : "r"(addr));
}
__device__ __forceinline__ void mma16(float* c, const uint32_t* a, const uint32_t* b) {
    asm volatile(
        "mma.sync.aligned.m16n8k16.row.col.f32.f16.f16.f32 "
        "{%0,%1,%2,%3}, {%4,%5,%6,%7}, {%8,%9}, {%0,%1,%2,%3};"
        : "+f"(c[0]), "+f"(c[1]), "+f"(c[2]), "+f"(c[3])
        : "r"(a[0]), "r"(a[1]), "r"(a[2]), "r"(a[3]), "r"(b[0]), "r"(b[1]));
}

// ---------------- kernel: fused w1/w3-convert + router -------------------
// blocks [0, WCONV_BLKS): fp16-convert w1/w3 only (w2 converts inside up_gemm)
// blocks [WCONV_BLKS, +T_TOK/8): router, 8 tokens per block
#define WCONV_BLKS 4096
__global__ __launch_bounds__(256) void prep_kernel(const float* __restrict__ x,
                                                   const float* __restrict__ wr,
                                                   const float* __restrict__ w1,
                                                   const float* __restrict__ w3) {
    __shared__ float sWr[D_DIM * E_NUM];   // used only by router blocks (32KB)

    if (blockIdx.x < WCONV_BLKS) {
        size_t i4 = (size_t)blockIdx.x * 256 + threadIdx.x;
        size_t n4 = (size_t)E_NUM * D_DIM * H_DIM / 4;
        if (i4 >= n4) return;
        {
            float4 v = *(const float4*)(w1 + i4 * 4);
            __half2 h0 = __floats2half2_rn(v.x, v.y), h1 = __floats2half2_rn(v.z, v.w);
            *(uint2*)(g_w1h + i4 * 4) = make_uint2(*(uint32_t*)&h0, *(uint32_t*)&h1);
        }
        {
            float4 v = *(const float4*)(w3 + i4 * 4);
            __half2 h0 = __floats2half2_rn(v.x, v.y), h1 = __floats2half2_rn(v.z, v.w);
            *(uint2*)(g_w3h + i4 * 4) = make_uint2(*(uint32_t*)&h0, *(uint32_t*)&h1);
        }
        return;
    }

    // ---- router part ----
    for (int i = threadIdx.x; i < D_DIM * E_NUM; i += blockDim.x) sWr[i] = wr[i];
    __syncthreads();

    int warp = threadIdx.x >> 5, lane = threadIdx.x & 31;
    int t = (blockIdx.x - WCONV_BLKS) * 8 + warp;
    if (t >= T_TOK) return;

    float acc[E_NUM];
#pragma unroll
    for (int e = 0; e < E_NUM; e++) acc[e] = 0.f;
    const float* xr = x + (size_t)t * D_DIM;
    __half* xo = g_Xh + (size_t)t * D_DIM;
    for (int d = lane; d < D_DIM; d += 32) {
        float xv = xr[d];
        xo[d] = __float2half_rn(xv);
#pragma unroll
        for (int e = 0; e < E_NUM; e++) acc[e] = fmaf(xv, sWr[d * E_NUM + e], acc[e]);
    }
#pragma unroll
    for (int off = 16; off > 0; off >>= 1)
#pragma unroll
        for (int e = 0; e < E_NUM; e++) acc[e] += __shfl_down_sync(0xffffffffu, acc[e], off);

    if (lane == 0) {
        float m = acc[0];
#pragma unroll
        for (int e = 1; e < E_NUM; e++) m = fmaxf(m, acc[e]);
        float p[E_NUM], s = 0.f;
#pragma unroll
        for (int e = 0; e < E_NUM; e++) { p[e] = expf(acc[e] - m); s += p[e]; }
        float inv = 1.f / s;
#pragma unroll
        for (int e = 0; e < E_NUM; e++) p[e] *= inv;

        int e0 = 0;
#pragma unroll
        for (int e = 1; e < E_NUM; e++) if (p[e] > p[e0]) e0 = e;
        int e1 = (e0 == 0) ? 1 : 0;
#pragma unroll
        for (int e = 0; e < E_NUM; e++) {
            if (e == e0) continue;
            if (p[e] > p[e1]) e1 = e;
        }
        int pos0 = atomicAdd(&g_count[e0], 1);
        g_entry[e0][pos0] = t * 2 + 0;
        g_gateW[e0][pos0] = p[e0];
        int pos1 = atomicAdd(&g_count[e1], 1);
        g_entry[e1][pos1] = t * 2 + 1;
        g_gateW[e1][pos1] = p[e1];
    }
}

// ---------------- GEMM tiling constants ----------------
#define BKT 64                          // K per smem tile (halves)
#define ASTR 144                        // A smem row stride bytes
#define BUSTR 144                       // up B k-row stride
#define BDSTR 272                       // down B k-row stride
#define A_TILE_B (128 * ASTR)           // 18432
#define BU_TILE_B (BKT * BUSTR)         // 9216 (per weight)
#define BD_TILE_B (BKT * BDSTR)         // 17408
#define STAGE_U (A_TILE_B + 2 * BU_TILE_B)  // 36864
#define STAGE_D (A_TILE_B + BD_TILE_B)      // 35840
#define UP_SMEM   (3 * STAGE_U)             // 110592
#define DOWN_SMEM (3 * STAGE_D)             // 107520

// ============================================================
// UP: per expert, U = silu(Xg@W1)*(Xg@W3). CTA: M=128, N=64 (each), K=1024.
// 3-stage ring, one barrier per k-iter. 256 thr, 2 CTAs/SM.
// blockIdx.z == E_NUM slice: converts w2 fp32->fp16 concurrently
// (rides under the GEMM's idle DRAM bandwidth; w2 needed only by down).
// ============================================================
__global__ __launch_bounds__(256, 2) void up_gemm_kernel(const float* __restrict__ w2) {
    if (blockIdx.z == E_NUM) {
        // w2 convert slice: 64 x 8 = 512 blocks cover 1M float4
        size_t bid = (size_t)blockIdx.x * 8 + blockIdx.y;   // 0..511
        size_t i4 = bid * (256 * 8) + threadIdx.x;
        size_t n4 = (size_t)E_NUM * H_DIM * D_DIM / 4;
#pragma unroll
        for (int r = 0; r < 8; r++, i4 += 256) {
            if (i4 < n4) {
                float4 v = *(const float4*)(w2 + i4 * 4);
                __half2 h0 = __floats2half2_rn(v.x, v.y), h1 = __floats2half2_rn(v.z, v.w);
                *(uint2*)(g_w2h + i4 * 4) = make_uint2(*(uint32_t*)&h0, *(uint32_t*)&h1);
            }
        }
        return;
    }

    const int e = blockIdx.z;
    const int count = g_count[e];
    const int m0 = blockIdx.x * 128;
    if (m0 >= count) return;
    const int n0 = blockIdx.y * 64;

    extern __shared__ __align__(128) char smem[];
    __shared__ int sTok[128];
    __shared__ int sEnt[128];

    const int tid = threadIdx.x;
    const int wid = tid >> 5, lane = tid & 31;
    const int warp_m = wid >> 1, warp_n = wid & 1;

    uint32_t base = smem_u32(smem);

    if (tid < 128) {
        int p = m0 + tid;
        int ent = (p < count) ? g_entry[e][p] : g_entry[e][0];
        sEnt[tid] = ent;
        sTok[tid] = ent >> 1;
    }
    __syncthreads();

    const __half* W1 = g_w1h + (size_t)e * D_DIM * H_DIM;   // [d][h] = [k][n]
    const __half* W3 = g_w3h + (size_t)e * D_DIM * H_DIM;

    auto load_tile = [&](int buf, int k0) {      // k0 in halves
        uint32_t aB  = base + buf * STAGE_U;
        uint32_t b1B = aB + A_TILE_B;
        uint32_t b3B = b1B + BU_TILE_B;
#pragma unroll
        for (int i = 0; i < 4; i++) {            // A: 128 m-rows x 8 chunks
            int c = tid + i * 256, row = c >> 3, q = c & 7;
            cp16(aB + row * ASTR + q * 16,
                 g_Xh + (size_t)sTok[row] * D_DIM + k0 + q * 8);
        }
#pragma unroll
        for (int i = 0; i < 2; i++) {            // B1: 64 k-rows x 8 chunks
            int c = tid + i * 256, row = c >> 3, q = c & 7;
            cp16(b1B + row * BUSTR + q * 16,
                 W1 + (size_t)(k0 + row) * H_DIM + n0 + q * 8);
        }
#pragma unroll
        for (int i = 0; i < 2; i++) {            // B3
            int c = tid + i * 256, row = c >> 3, q = c & 7;
            cp16(b3B + row * BUSTR + q * 16,
                 W3 + (size_t)(k0 + row) * H_DIM + n0 + q * 8);
        }
    };

    load_tile(0, 0);       CP_COMMIT();
    load_tile(1, BKT);     CP_COMMIT();

    float acc1[2][4][4] = {};
    float acc3[2][4][4] = {};

    uint32_t aOff0 = (uint32_t)(warp_m * 32 + (lane & 15)) * ASTR + (lane >> 4) * 16;
    uint32_t aOff1 = aOff0 + 16 * ASTR;
    uint32_t bOffT = (uint32_t)((lane & 7) + ((lane >> 3) & 1) * 8) * BUSTR
                   + (uint32_t)(warp_n * 32 + ((lane >> 4) & 1) * 8) * 2;

    const int lrow = lane >> 2;
    const int lcol = lane & 3;
    const int NT = D_DIM / BKT;      // 16

    for (int kt = 0; kt < NT; kt++) {
        const int cur = kt % 3;
        CP_WAIT1();
        __syncthreads();
        if (kt + 2 < NT) load_tile((kt + 2) % 3, (kt + 2) * BKT);
        CP_COMMIT();

        uint32_t aS  = base + cur * STAGE_U;
        uint32_t b1S = aS + A_TILE_B;
        uint32_t b3S = b1S + BU_TILE_B;

#pragma unroll
        for (int ks = 0; ks < BKT / 16; ks++) {
            uint32_t a[2][4], b1[2][4], b3[2][4];
            ldsm4(a[0], aS + aOff0 + ks * 32);
            ldsm4(a[1], aS + aOff1 + ks * 32);
#pragma unroll
            for (int p = 0; p < 2; p++) {
                ldsm4t(b1[p], b1S + bOffT + p * 32 + ks * (16 * BUSTR));
                ldsm4t(b3[p], b3S + bOffT + p * 32 + ks * (16 * BUSTR));
            }
#pragma unroll
            for (int mt = 0; mt < 2; mt++)
#pragma unroll
                for (int p = 0; p < 2; p++) {
                    mma16(acc1[mt][2 * p + 0], a[mt], &b1[p][0]);
                    mma16(acc1[mt][2 * p + 1], a[mt], &b1[p][2]);
                    mma16(acc3[mt][2 * p + 0], a[mt], &b3[p][0]);
                    mma16(acc3[mt][2 * p + 1], a[mt], &b3[p][2]);
                }
        }
    }

    // epilogue: silu(u1)*u3 -> g_U (fp16); fast __expf
#pragma unroll
    for (int mt = 0; mt < 2; mt++) {
#pragma unroll
        for (int half = 0; half < 2; half++) {
            int r = warp_m * 32 + mt * 16 + lrow + half * 8;
            if (m0 + r < count) {
                __half* urow = g_U + (size_t)sEnt[r] * H_DIM;
#pragma unroll
                for (int nt = 0; nt < 4; nt++) {
                    int cbase = n0 + warp_n * 32 + nt * 8 + 2 * lcol;
                    float z0 = acc1[mt][nt][half * 2 + 0];
                    float z1 = acc1[mt][nt][half * 2 + 1];
                    float u0 = z0 / (1.f + __expf(-z0)) * acc3[mt][nt][half * 2 + 0];
                    float u1 = z1 / (1.f + __expf(-z1)) * acc3[mt][nt][half * 2 + 1];
                    *(__half2*)(urow + cbase) = __floats2half2_rn(u0, u1);
                }
            }
        }
    }
}

// ============================================================
// DOWN: per expert, Y = gate * (U@W2) stored fp16 per (token,slot).
// CTA: M=128, N=128, K=512. 3-stage ring, one barrier per iter.
// ============================================================
__global__ __launch_bounds__(256, 2) void down_gemm_kernel() {
    const int e = blockIdx.z;
    const int count = g_count[e];
    const int m0 = blockIdx.x * 128;
    if (m0 >= count) return;
    const int n0 = blockIdx.y * 128;

    extern __shared__ __align__(128) char smem[];
    __shared__ int   sEnt[128];
    __shared__ float sGate[128];

    const int tid = threadIdx.x;
    const int wid = tid >> 5, lane = tid & 31;
    const int warp_m = wid >> 1, warp_n = wid & 1;

    uint32_t base = smem_u32(smem);

    if (tid < 128) {
        int p = m0 + tid;
        sEnt[tid]  = (p < count) ? g_entry[e][p] : g_entry[e][0];
        sGate[tid] = (p < count) ? g_gateW[e][p] : 0.f;
    }
    __syncthreads();

    const __half* W2 = g_w2h + (size_t)e * H_DIM * D_DIM;   // [h][d] = [k][n]

    auto load_tile = [&](int buf, int k0) {
        uint32_t aB = base + buf * STAGE_D;
        uint32_t bB = aB + A_TILE_B;
#pragma unroll
        for (int i = 0; i < 4; i++) {            // A: 128 m-rows x 8 chunks
            int c = tid + i * 256, row = c >> 3, q = c & 7;
            cp16(aB + row * ASTR + q * 16,
                 g_U + (size_t)sEnt[row] * H_DIM + k0 + q * 8);
        }
#pragma unroll
        for (int i = 0; i < 4; i++) {            // B: 64 k-rows x 16 chunks
            int c = tid + i * 256, row = c >> 4, q = c & 15;
            cp16(bB + row * BDSTR + q * 16,
                 W2 + (size_t)(k0 + row) * D_DIM + n0 + q * 8);
        }
    };

    load_tile(0, 0);       CP_COMMIT();
    load_tile(1, BKT);     CP_COMMIT();

    float acc[2][8][4] = {};

    uint32_t aOff0 = (uint32_t)(warp_m * 32 + (lane & 15)) * ASTR + (lane >> 4) * 16;
    uint32_t aOff1 = aOff0 + 16 * ASTR;
    uint32_t bOffT = (uint32_t)((lane & 7) + ((lane >> 3) & 1) * 8) * BDSTR
                   + (uint32_t)(warp_n * 64 + ((lane >> 4) & 1) * 8) * 2;

    const int lrow = lane >> 2;
    const int lcol = lane & 3;
    const int NT = H_DIM / BKT;   // 8

    for (int kt = 0; kt < NT; kt++) {
        const int cur = kt % 3;
        CP_WAIT1();
        __syncthreads();
        if (kt + 2 < NT) load_tile((kt + 2) % 3, (kt + 2) * BKT);
        CP_COMMIT();

        uint32_t aS = base + cur * STAGE_D;
        uint32_t bS = aS + A_TILE_B;

#pragma unroll
        for (int ks = 0; ks < BKT / 16; ks++) {
            uint32_t a[2][4], b[4][4];
            ldsm4(a[0], aS + aOff0 + ks * 32);
            ldsm4(a[1], aS + aOff1 + ks * 32);
#pragma unroll
            for (int p = 0; p < 4; p++)
                ldsm4t(b[p], bS + bOffT + p * 32 + ks * (16 * BDSTR));
#pragma unroll
            for (int mt = 0; mt < 2; mt++)
#pragma unroll
                for (int p = 0; p < 4; p++) {
                    mma16(acc[mt][2 * p + 0], a[mt], &b[p][0]);
                    mma16(acc[mt][2 * p + 1], a[mt], &b[p][2]);
                }
        }
    }

    // epilogue: fp16 store of gate*acc per slot
#pragma unroll
    for (int mt = 0; mt < 2; mt++) {
#pragma unroll
        for (int half = 0; half < 2; half++) {
            int r = warp_m * 32 + mt * 16 + lrow + half * 8;
            if (m0 + r < count) {
                float g = sGate[r];
                __half* yrow = g_Y + (size_t)sEnt[r] * D_DIM;
#pragma unroll
                for (int nt = 0; nt < 8; nt++) {
                    int cbase = n0 + warp_n * 64 + nt * 8 + 2 * lcol;
                    *(__half2*)(yrow + cbase) =
                        __floats2half2_rn(g * acc[mt][nt][half * 2 + 0],
                                          g * acc[mt][nt][half * 2 + 1]);
                }
            }
        }
    }
}

// ---------------- kernel: combine two fp16 slots + reset g_count --------
__global__ void combine_kernel(float* __restrict__ out) {
    if (blockIdx.x == 0 && threadIdx.x < E_NUM) g_count[threadIdx.x] = 0;

    size_t idx4 = (size_t)blockIdx.x * blockDim.x + threadIdx.x;
    size_t total4 = (size_t)T_TOK * D_DIM / 4;
    if (idx4 >= total4) return;
    size_t bofs = idx4 * 4;
    size_t t = bofs >> 10;
    size_t d = bofs & (D_DIM - 1);
    const uint2 pa = *(const uint2*)(g_Y + ((size_t)(2 * t) * D_DIM + d));
    const uint2 pb = *(const uint2*)(g_Y + ((size_t)(2 * t + 1) * D_DIM + d));
    float2 a0 = __half22float2(*(const __half2*)&pa.x);
    float2 a1 = __half22float2(*(const __half2*)&pa.y);
    float2 b0 = __half22float2(*(const __half2*)&pb.x);
    float2 b1 = __half22float2(*(const __half2*)&pb.y);
    float4 r;
    r.x = a0.x + b0.x; r.y = a0.y + b0.y;
    r.z = a1.x + b1.x; r.w = a1.y + b1.y;
    asm volatile("st.global.cs.v4.f32 [%0], {%1,%2,%3,%4};"
                 :: "l"(out + bofs), "f"(r.x), "f"(r.y), "f"(r.z), "f"(r.w) : "memory");
}

// ---------------- launch ----------------
extern "C" void kernel_launch(void* const* d_in, const int* in_sizes, int n_in,
                              void* d_out, int out_size) {
    const float* x  = (const float*)d_in[0];
    const float* wr = (const float*)d_in[1];
    const float* w1 = (const float*)d_in[2];
    const float* w2 = (const float*)d_in[3];
    const float* w3 = (const float*)d_in[4];
    float* out = (float*)d_out;

    cudaFuncSetAttribute(up_gemm_kernel,   cudaFuncAttributeMaxDynamicSharedMemorySize, UP_SMEM);
    cudaFuncSetAttribute(down_gemm_kernel, cudaFuncAttributeMaxDynamicSharedMemorySize, DOWN_SMEM);

    // fused w1/w3-convert + router
    prep_kernel<<<WCONV_BLKS + T_TOK / 8, 256>>>(x, wr, w1, w3);

    {
        // z slices 0..7: expert GEMMs; z == 8: w2 fp16 convert (overlapped)
        dim3 g(T_TOK / 128, H_DIM / 64, E_NUM + 1);   // (64, 8, 9)
        up_gemm_kernel<<<g, 256, UP_SMEM>>>(w2);
    }
    {
        dim3 g(T_TOK / 128, D_DIM / 128, E_NUM);  // (64, 8, 8)
        down_gemm_kernel<<<g, 256, DOWN_SMEM>>>();
    }

    size_t total4 = (size_t)T_TOK * D_DIM / 4;
    combine_kernel<<<(unsigned)((total4 + 255) / 256), 256>>>(out);
}